// round 4
// baseline (speedup 1.0000x reference)
#include <cuda_runtime.h>
#include <cuda_bf16.h>
#include <cstddef>

// Problem constants (ResidualBlock: N=50000, K=16, DIM=256, LeakyReLU slope 0.2)
#define PN    50000
#define PK    16
#define PDIM  256
#define SLOPE 0.2f

// ---------------------------------------------------------------------------
// Scratch (no allocations allowed -> __device__ globals)
// ---------------------------------------------------------------------------
__device__ float g_a0[(size_t)PN * 64];    // init MLP output      [N, 64]
__device__ float g_a1[(size_t)PN * 128];   // LFA1 output          [N, 128]
__device__ float g_a2[(size_t)PN * 256];   // LFA2 output          [N, 256]

// ---------------------------------------------------------------------------
// Packed f32x2 helpers (sm_103a FFMA2 — only reachable via PTX)
// ---------------------------------------------------------------------------
__device__ __forceinline__ unsigned long long ffma2(unsigned long long a,
                                                    unsigned long long b,
                                                    unsigned long long c)
{
    unsigned long long d;
    asm("fma.rn.f32x2 %0, %1, %2, %3;" : "=l"(d) : "l"(a), "l"(b), "l"(c));
    return d;
}

__device__ __forceinline__ float2 ull_as_f2(unsigned long long u)
{
    float2 r;
    asm("mov.b64 {%0, %1}, %2;" : "=f"(r.x), "=f"(r.y) : "l"(u));
    return r;
}

// ---------------------------------------------------------------------------
// FFMA2 micro-step: 8 row-dup pairs (a,a) x TNP natural col pairs (b0,b1)
// a_ points at row-duplicated A frag (16 floats), b_ at natural B frag.
// ---------------------------------------------------------------------------
template <int TNP>
__device__ __forceinline__ void mma_step(const float* a_, const float* b_,
                                         unsigned long long (&acc)[8][TNP])
{
    unsigned long long ad[8];
    const ulonglong2* ap = (const ulonglong2*)a_;
    ulonglong2 t0 = ap[0], t1 = ap[1], t2 = ap[2], t3 = ap[3];
    ad[0] = t0.x; ad[1] = t0.y; ad[2] = t1.x; ad[3] = t1.y;
    ad[4] = t2.x; ad[5] = t2.y; ad[6] = t3.x; ad[7] = t3.y;

    unsigned long long bp[TNP];
    const ulonglong2* bq = (const ulonglong2*)b_;
    ulonglong2 u0 = bq[0];
    bp[0] = u0.x; bp[1] = u0.y;
    if constexpr (TNP == 4) {
        ulonglong2 u1 = bq[1];
        bp[2] = u1.x; bp[3] = u1.y;
    }

#pragma unroll
    for (int r = 0; r < 8; r++)
#pragma unroll
        for (int p = 0; p < TNP; p++)
            acc[r][p] = ffma2(ad[r], bp[p], acc[r][p]);
}

// ---------------------------------------------------------------------------
// GEMM: C[M,Ncols] = leaky(A[M,Kd] @ W[Kd,Ncols] + bias) (+ optional res add)
// BM=128, BK=8, TM=8; BN_/TN_ = 128/8 or 64/4; 256 threads; FFMA2 inner loop.
// A tile stored ROW-DUPLICATED in smem -> packed (a,a) pairs read directly.
// ---------------------------------------------------------------------------
template <int BN_, int TN_>
__global__ __launch_bounds__(256, 2) void gemm_leaky(
    const float* __restrict__ A, const float* __restrict__ W,
    const float* __restrict__ bias, const float* __restrict__ res,
    float* __restrict__ C, int M, int Kd, int Ncols)
{
    constexpr int BM = 128, BK = 8;
    constexpr int AS = 2 * BM + 4;       // dup-row stride (multiple of 4 floats)
    constexpr int TNP = TN_ / 2;

    __shared__ __align__(16) float Asd[2][BK][AS];
    __shared__ __align__(16) float Bs[2][BK][BN_];

    const int tid  = threadIdx.x;
    const int tx   = tid & 15;           // 16 col groups
    const int ty   = tid >> 4;           // 16 row groups (8 rows each)
    const int row0 = blockIdx.x * BM;
    const int col0 = blockIdx.y * BN_;

    // A loader: float4 of row lr at k-offset lk
    const int lr = tid >> 1;
    const int lk = (tid & 1) << 2;
    const bool aok = (row0 + lr) < M;
    const float* Ag = A + (size_t)(row0 + lr) * Kd + lk;

    // B loader
    const int bk = tid >> 5;                       // 0..7
    const int bc = (BN_ == 128) ? ((tid & 31) << 2) : ((tid & 31) << 1);
    const float* Bg = W + (size_t)bk * Ncols + col0 + bc;

    unsigned long long acc[8][TNP];
#pragma unroll
    for (int r = 0; r < 8; r++)
#pragma unroll
        for (int p = 0; p < TNP; p++) acc[r][p] = 0ull;

    // ---- preload k0 = 0 ----
    float4 aReg = aok ? *(const float4*)(Ag)
                      : make_float4(0.f, 0.f, 0.f, 0.f);
    float4 bReg;
    if constexpr (BN_ == 128) {
        bReg = *(const float4*)(Bg);
    } else {
        float2 t = *(const float2*)(Bg);
        bReg.x = t.x; bReg.y = t.y; bReg.z = 0.f; bReg.w = 0.f;
    }

    int buf = 0;
    {
        float av[4] = {aReg.x, aReg.y, aReg.z, aReg.w};
#pragma unroll
        for (int j = 0; j < 4; j++) {
            Asd[buf][lk + j][2 * lr]     = av[j];
            Asd[buf][lk + j][2 * lr + 1] = av[j];
        }
        if constexpr (BN_ == 128) {
            *(float4*)&Bs[buf][bk][bc] = bReg;
        } else {
            Bs[buf][bk][bc]     = bReg.x;
            Bs[buf][bk][bc + 1] = bReg.y;
        }
    }
    __syncthreads();

    for (int k0 = 0; k0 < Kd; k0 += BK) {
        const bool nxt = (k0 + BK) < Kd;
        float4 aN, bN;
        if (nxt) {
            aN = aok ? *(const float4*)(Ag + k0 + BK)
                     : make_float4(0.f, 0.f, 0.f, 0.f);
            if constexpr (BN_ == 128) {
                bN = *(const float4*)(Bg + (size_t)(k0 + BK) * Ncols);
            } else {
                float2 t = *(const float2*)(Bg + (size_t)(k0 + BK) * Ncols);
                bN.x = t.x; bN.y = t.y; bN.z = 0.f; bN.w = 0.f;
            }
        }

#pragma unroll
        for (int kk = 0; kk < BK; kk++)
            mma_step<TNP>(&Asd[buf][kk][ty * 16], &Bs[buf][kk][tx * TN_], acc);

        if (nxt) {
            const int nb = buf ^ 1;
            float av[4] = {aN.x, aN.y, aN.z, aN.w};
#pragma unroll
            for (int j = 0; j < 4; j++) {
                Asd[nb][lk + j][2 * lr]     = av[j];
                Asd[nb][lk + j][2 * lr + 1] = av[j];
            }
            if constexpr (BN_ == 128) {
                *(float4*)&Bs[nb][bk][bc] = bN;
            } else {
                Bs[nb][bk][bc]     = bN.x;
                Bs[nb][bk][bc + 1] = bN.y;
            }
            __syncthreads();
            buf = nb;
        }
    }

    // ---- epilogue ----
    float bv[TN_];
    {
        const float* bp = bias + col0 + tx * TN_;
        float4 b0 = *(const float4*)(bp);
        bv[0] = b0.x; bv[1] = b0.y; bv[2] = b0.z; bv[3] = b0.w;
        if constexpr (TN_ == 8) {
            float4 b1 = *(const float4*)(bp + 4);
            bv[4] = b1.x; bv[5] = b1.y; bv[6] = b1.z; bv[7] = b1.w;
        }
    }

#pragma unroll
    for (int r = 0; r < 8; r++) {
        const int row = row0 + ty * 8 + r;
        if (row >= M) break;            // rows per thread are consecutive
        float o[TN_];
#pragma unroll
        for (int p = 0; p < TNP; p++) {
            float2 f = ull_as_f2(acc[r][p]);
            o[2 * p]     = f.x;
            o[2 * p + 1] = f.y;
        }
#pragma unroll
        for (int j = 0; j < TN_; j++) {
            float v = o[j] + bv[j];
            o[j] = v >= 0.f ? v : SLOPE * v;
        }
        const size_t off = (size_t)row * Ncols + col0 + tx * TN_;
        if (res) {
            const float4 r0 = *(const float4*)(res + off);
            o[0] += r0.x; o[1] += r0.y; o[2] += r0.z; o[3] += r0.w;
            if constexpr (TN_ == 8) {
                const float4 r1 = *(const float4*)(res + off + 4);
                o[4] += r1.x; o[5] += r1.y; o[6] += r1.z; o[7] += r1.w;
            }
        }
        *(float4*)(C + off) = make_float4(o[0], o[1], o[2], o[3]);
        if constexpr (TN_ == 8)
            *(float4*)(C + off + 4) = make_float4(o[4], o[5], o[6], o[7]);
    }
}

// ---------------------------------------------------------------------------
// LFA: out[n] = [ mean_k leaky(geom[n,k,:4] @ wg + bg),  mean_k feat[idx[n,k]] ]
// One warp per point. Geom-MLP weights hoisted to registers (zero LDS in the
// hot loop); gather issued in register batches for MLP (16 loads in flight).
// ---------------------------------------------------------------------------
template <int D>
__global__ __launch_bounds__(256) void lfa_kernel(
    const float* __restrict__ geom, const int* __restrict__ idx,
    const float* __restrict__ feat, float* __restrict__ out,
    const float* __restrict__ wg, const float* __restrict__ bg, int N)
{
    __shared__ float sw[4][D];
    __shared__ float sb[D];
    for (int i = threadIdx.x; i < 4 * D; i += blockDim.x) sw[i / D][i % D] = wg[i];
    for (int i = threadIdx.x; i < D; i += blockDim.x) sb[i] = bg[i];
    __syncthreads();

    constexpr int DPL = D / 32;                 // feature dims per lane
    constexpr int KB  = (DPL == 2) ? 8 : 4;     // gather batch size (16 LDG in flight)
    const int warp = threadIdx.x >> 5;
    const int lane = threadIdx.x & 31;
    const int wpb  = blockDim.x >> 5;

    // Hoist weights/bias into registers (per-lane, invariant over points)
    float w0[DPL], w1[DPL], w2[DPL], w3[DPL], bb[DPL];
#pragma unroll
    for (int q = 0; q < DPL; q++) {
        const int d = lane + 32 * q;
        w0[q] = sw[0][d]; w1[q] = sw[1][d];
        w2[q] = sw[2][d]; w3[q] = sw[3][d];
        bb[q] = sb[d];
    }

    const float inv = 1.0f / (float)PK;

    for (int n = blockIdx.x * wpb + warp; n < N; n += gridDim.x * wpb) {
        float accG[DPL], accF[DPL];
#pragma unroll
        for (int q = 0; q < DPL; q++) { accG[q] = 0.f; accF[q] = 0.f; }

        // indices (warp-uniform, vectorized)
        int rows[PK];
        const int4* ip = (const int4*)(idx + (size_t)n * PK);
#pragma unroll
        for (int k4 = 0; k4 < PK / 4; k4++) {
            int4 r = ip[k4];
            rows[4 * k4 + 0] = r.x; rows[4 * k4 + 1] = r.y;
            rows[4 * k4 + 2] = r.z; rows[4 * k4 + 3] = r.w;
        }

        // geom MLP (pure FFMA, broadcast loads)
        const float4* gp = (const float4*)(geom + (size_t)n * (PK * 4));
#pragma unroll
        for (int k = 0; k < PK; k++) {
            const float4 g = gp[k];
#pragma unroll
            for (int q = 0; q < DPL; q++) {
                float v = bb[q];
                v = fmaf(g.x, w0[q], v);
                v = fmaf(g.y, w1[q], v);
                v = fmaf(g.z, w2[q], v);
                v = fmaf(g.w, w3[q], v);
                v = v >= 0.f ? v : SLOPE * v;
                accG[q] += v;
            }
        }

        // gather, batched for memory-level parallelism
#pragma unroll
        for (int kb = 0; kb < PK; kb += KB) {
            float t[KB][DPL];
#pragma unroll
            for (int j = 0; j < KB; j++) {
                const float* fr = feat + (size_t)rows[kb + j] * D;
#pragma unroll
                for (int q = 0; q < DPL; q++)
                    t[j][q] = fr[lane + 32 * q];      // coalesced 128B/warp
            }
#pragma unroll
            for (int j = 0; j < KB; j++)
#pragma unroll
                for (int q = 0; q < DPL; q++)
                    accF[q] += t[j][q];
        }

        float* o = out + (size_t)n * (2 * D);
#pragma unroll
        for (int q = 0; q < DPL; q++) {
            o[lane + 32 * q]     = accG[q] * inv;
            o[D + lane + 32 * q] = accF[q] * inv;
        }
    }
}

// ---------------------------------------------------------------------------
// Launch
// ---------------------------------------------------------------------------
extern "C" void kernel_launch(void* const* d_in, const int* in_sizes, int n_in,
                              void* d_out, int out_size)
{
    const float* x      = (const float*)d_in[0];   // input_features [N,256]
    const float* geom   = (const float*)d_in[1];   // geom_features  [N,16,4]
    const int*   idx    = (const int*)  d_in[2];   // closest_indices[N,16]
    const float* w_res  = (const float*)d_in[3];   // [256,256]
    const float* b_res  = (const float*)d_in[4];   // [256]
    const float* w_init = (const float*)d_in[5];   // [256,64]
    const float* b_init = (const float*)d_in[6];   // [64]
    const float* w_g1   = (const float*)d_in[7];   // [4,64]
    const float* b_g1   = (const float*)d_in[8];   // [64]
    const float* w_g2   = (const float*)d_in[9];   // [4,128]
    const float* b_g2   = (const float*)d_in[10];  // [128]
    const float* w_fin  = (const float*)d_in[11];  // [256,256]
    const float* b_fin  = (const float*)d_in[12];  // [256]
    float* out = (float*)d_out;

    float *a0, *a1, *a2;
    cudaGetSymbolAddress((void**)&a0, g_a0);
    cudaGetSymbolAddress((void**)&a1, g_a1);
    cudaGetSymbolAddress((void**)&a2, g_a2);

    const int M = PN;
    const dim3 gBig((M + 127) / 128, PDIM / 128);   // 391 x 2
    const dim3 gInit((M + 127) / 128, 1);           // 391 x 1
    const int  lfaBlocks = (M + 7) / 8;             // 8 warps/block

    // 1) residual -> d_out (covers every output element: un-poisons d_out)
    gemm_leaky<128, 8><<<gBig, 256>>>(x, w_res, b_res, nullptr, out, M, PDIM, PDIM);
    // 2) a0 = leaky(x @ w_init + b)
    gemm_leaky<64, 4><<<gInit, 256>>>(x, w_init, b_init, nullptr, a0, M, PDIM, 64);
    // 3) LFA1: a1 = [mean leaky(geom@w_g1+b), mean gather(a0)]
    lfa_kernel<64><<<lfaBlocks, 256>>>(geom, idx, a0, a1, w_g1, b_g1, M);
    // 4) LFA2: a2 = [mean leaky(geom@w_g2+b), mean gather(a1)]
    lfa_kernel<128><<<lfaBlocks, 256>>>(geom, idx, a1, a2, w_g2, b_g2, M);
    // 5) out = leaky(a2 @ w_fin + b) + residual(d_out)
    gemm_leaky<128, 8><<<gBig, 256>>>(a2, w_fin, b_fin, out, out, M, PDIM, PDIM);
}

// round 6
// speedup vs baseline: 1.8658x; 1.8658x over previous
#include <cuda_runtime.h>
#include <cuda_bf16.h>
#include <cstdint>
#include <cstddef>

// Problem constants (ResidualBlock: N=50000, K=16, DIM=256, LeakyReLU slope 0.2)
#define PN    50000
#define PK    16
#define PDIM  256
#define SLOPE 0.2f

typedef __nv_bfloat16 bf16;

// ---------------------------------------------------------------------------
// Scratch (__device__ globals; no allocations allowed)
// ---------------------------------------------------------------------------
__device__ __align__(16) float g_a0[(size_t)PN * 64];     // init MLP out [N,64]
__device__ __align__(16) float g_a1[(size_t)PN * 128];    // LFA1 out     [N,128]
__device__ __align__(16) bf16 g_xhi[(size_t)PN * 256];
__device__ __align__(16) bf16 g_xlo[(size_t)PN * 256];
__device__ __align__(16) bf16 g_a2hi[(size_t)PN * 256];
__device__ __align__(16) bf16 g_a2lo[(size_t)PN * 256];
__device__ __align__(16) bf16 g_wres_hi[256 * 256];   // transposed: [n][k]
__device__ __align__(16) bf16 g_wres_lo[256 * 256];
__device__ __align__(16) bf16 g_winit_hi[64 * 256];
__device__ __align__(16) bf16 g_winit_lo[64 * 256];
__device__ __align__(16) bf16 g_wfin_hi[256 * 256];
__device__ __align__(16) bf16 g_wfin_lo[256 * 256];

// ---------------------------------------------------------------------------
// PTX helpers (all plain-sm_103-legal: cp.async, ldmatrix, mma.sync)
// ---------------------------------------------------------------------------
__device__ __forceinline__ uint32_t smem_u32(const void* p) {
    uint32_t a;
    asm("{ .reg .u64 t; cvta.to.shared.u64 t, %1; cvt.u32.u64 %0, t; }"
        : "=r"(a) : "l"(p));
    return a;
}

#define CP16(dst, src) \
    asm volatile("cp.async.cg.shared.global [%0], [%1], 16;" \
                 :: "r"(dst), "l"(src) : "memory")
#define CP_COMMIT() asm volatile("cp.async.commit_group;" ::: "memory")
#define CP_WAIT0()  asm volatile("cp.async.wait_group 0;" ::: "memory")
#define CP_WAIT1()  asm volatile("cp.async.wait_group 1;" ::: "memory")

#define LDSM_X4(r, addr) \
    asm volatile("ldmatrix.sync.aligned.m8n8.x4.shared.b16 {%0,%1,%2,%3}, [%4];" \
                 : "=r"((r)[0]), "=r"((r)[1]), "=r"((r)[2]), "=r"((r)[3]) \
                 : "r"(addr))

#define MMA16816(d, a, b) \
    asm volatile("mma.sync.aligned.m16n8k16.row.col.f32.bf16.bf16.f32 " \
                 "{%0,%1,%2,%3},{%4,%5,%6,%7},{%8,%9},{%0,%1,%2,%3};" \
                 : "+f"((d)[0]), "+f"((d)[1]), "+f"((d)[2]), "+f"((d)[3]) \
                 : "r"((a)[0]), "r"((a)[1]), "r"((a)[2]), "r"((a)[3]), \
                   "r"((b)[0]), "r"((b)[1]))

// ---------------------------------------------------------------------------
// Prep kernels (bf16 hi/lo split)
// ---------------------------------------------------------------------------
__device__ __forceinline__ void bf16_split(float v, bf16& h, bf16& l)
{
    h = __float2bfloat16(v);
    l = __float2bfloat16(v - __bfloat162float(h));
}

__global__ __launch_bounds__(256) void split_x_kernel(
    const float* __restrict__ x, bf16* __restrict__ hi,
    bf16* __restrict__ lo, int n4)
{
    int i = blockIdx.x * blockDim.x + threadIdx.x;
    if (i >= n4) return;
    float4 v = ((const float4*)x)[i];
    bf16 h0, h1, h2, h3, l0, l1, l2, l3;
    bf16_split(v.x, h0, l0); bf16_split(v.y, h1, l1);
    bf16_split(v.z, h2, l2); bf16_split(v.w, h3, l3);
    __nv_bfloat162 hA = {h0, h1}, hB = {h2, h3}, lA = {l0, l1}, lB = {l2, l3};
    uint2 ho, loo;
    ho.x  = *(uint32_t*)&hA; ho.y  = *(uint32_t*)&hB;
    loo.x = *(uint32_t*)&lA; loo.y = *(uint32_t*)&lB;
    ((uint2*)hi)[i] = ho;
    ((uint2*)lo)[i] = loo;
}

// W[K=256, Ncols] f32 -> transposed split bf16 Wt[Ncols][256]
__global__ __launch_bounds__(256) void transpose_split_kernel(
    const float* __restrict__ W, bf16* __restrict__ hi,
    bf16* __restrict__ lo, int Ncols)
{
    int i = blockIdx.x * blockDim.x + threadIdx.x;
    if (i >= Ncols * 256) return;
    int n = i >> 8, k = i & 255;
    bf16 h, l;
    bf16_split(W[(size_t)k * Ncols + n], h, l);
    hi[i] = h;
    lo[i] = l;
}

// ---------------------------------------------------------------------------
// Tensor-core GEMM via mma.sync (HMMA):
//   C[M,Nout] = leaky(A[M,256] @ Wt^T + bias) (+ optional res)
// A given as bf16 hi/lo split; Wt[Nout][256] as hi/lo split.
// 3-pass split folded into a 12-chunk virtual-K loop, fp32 accumulators.
// CTA: BM=128 x BN x BK=64, 256 threads, warp grid 2(M) x 4(N),
// warp tile 64 x (BN/4). cp.async double buffer, +8 elem padded smem rows.
// ---------------------------------------------------------------------------
template <int BN>
__global__ __launch_bounds__(256) void gemm_mma(
    const bf16* __restrict__ Ahi, const bf16* __restrict__ Alo,
    const bf16* __restrict__ Bhi, const bf16* __restrict__ Blo,
    const float* __restrict__ bias, const float* __restrict__ res,
    float* __restrict__ C, int M, int Nout)
{
    constexpr int BM = 128, BK = 64, SA = BK + 8;     // padded row stride
    constexpr int ABYTES = BM * SA * 2;               // per stage
    constexpr int BBYTES = BN * SA * 2;
    constexpr int NT8 = BN / 32;                      // n8 tiles per warp (4|2)
    constexpr int NPAIR = NT8 / 2;                    // ldmatrix.x4 pairs (2|1)
    constexpr int NIT = 12;                           // 3 passes x 4 k-chunks

    extern __shared__ __align__(16) char smem[];
    const uint32_t sa_u = smem_u32(smem);
    const uint32_t sb_u = sa_u + 2 * ABYTES;

    const int tid  = threadIdx.x;
    const int lane = tid & 31;
    const int wid  = tid >> 5;
    const int warpM0 = (wid >> 2) * 64;
    const int warpN0 = (wid & 3) * (BN / 4);
    const int row0 = blockIdx.x * BM;
    const int col0 = blockIdx.y * BN;

    // loader lane mapping: 8 threads per 64-elem row (16B each), 32 rows/step
    const int lr = tid >> 3;
    const int lc = (tid & 7) * 8;

    float acc[4][NT8][4];
#pragma unroll
    for (int mt = 0; mt < 4; mt++)
#pragma unroll
        for (int nt = 0; nt < NT8; nt++)
#pragma unroll
            for (int j = 0; j < 4; j++) acc[mt][nt][j] = 0.f;

    auto load_tile = [&](int it, int stage) {
        const int pass = it >> 2, kc = it & 3;
        const bf16* Ap = (pass == 2) ? Alo : Ahi;   // passes: hh, hl, lh
        const bf16* Bp = (pass == 1) ? Blo : Bhi;
        const int kbase = kc * BK;
#pragma unroll
        for (int i = 0; i < 4; i++) {               // A: 128 rows
            int r = lr + 32 * i;
            int gr = row0 + r;
            if (gr > M - 1) gr = M - 1;             // clamp; rows discarded later
            const void* src = Ap + (size_t)gr * 256 + kbase + lc;
            CP16(sa_u + stage * ABYTES + (r * SA + lc) * 2, src);
        }
#pragma unroll
        for (int i = 0; i < BN / 32; i++) {         // B: BN rows
            int r = lr + 32 * i;
            const void* src = Bp + (size_t)(col0 + r) * 256 + kbase + lc;
            CP16(sb_u + stage * BBYTES + (r * SA + lc) * 2, src);
        }
        CP_COMMIT();
    };

    load_tile(0, 0);

    for (int it = 0; it < NIT; it++) {
        const int stage = it & 1;
        if (it + 1 < NIT) {
            load_tile(it + 1, stage ^ 1);
            CP_WAIT1();
        } else {
            CP_WAIT0();
        }
        __syncthreads();

        // fragment base addresses for this stage
        const uint32_t aBase = sa_u + stage * ABYTES
            + ((warpM0 + (lane & 15)) * SA + (lane >> 4) * 8) * 2;
        const uint32_t bBase = sb_u + stage * BBYTES
            + ((warpN0 + ((lane >> 4) * 8) + (lane & 7)) * SA
               + ((lane >> 3) & 1) * 8) * 2;

#pragma unroll
        for (int ks = 0; ks < 4; ks++) {            // 4 x k16 per chunk
            uint32_t a[4][4];
#pragma unroll
            for (int mt = 0; mt < 4; mt++)
                LDSM_X4(a[mt], aBase + mt * (16 * SA * 2) + ks * 32);

            uint32_t b[NT8][2];
#pragma unroll
            for (int np = 0; np < NPAIR; np++) {
                uint32_t t[4];
                LDSM_X4(t, bBase + np * (16 * SA * 2) + ks * 32);
                b[2 * np][0] = t[0]; b[2 * np][1] = t[1];
                b[2 * np + 1][0] = t[2]; b[2 * np + 1][1] = t[3];
            }

#pragma unroll
            for (int mt = 0; mt < 4; mt++)
#pragma unroll
                for (int nt = 0; nt < NT8; nt++)
                    MMA16816(acc[mt][nt], a[mt], b[nt]);
        }
        __syncthreads();
    }

    // ---- epilogue: bias + leaky (+ res), f32 out ----
    const int erow = (lane >> 2);
    const int ecol = (lane & 3) * 2;
#pragma unroll
    for (int mt = 0; mt < 4; mt++) {
#pragma unroll
        for (int nt = 0; nt < NT8; nt++) {
            const int col = col0 + warpN0 + nt * 8 + ecol;
            const float2 b2 = *(const float2*)(bias + col);
#pragma unroll
            for (int h = 0; h < 2; h++) {
                const int row = row0 + warpM0 + mt * 16 + erow + h * 8;
                if (row >= M) continue;
                float vx = acc[mt][nt][2 * h]     + b2.x;
                float vy = acc[mt][nt][2 * h + 1] + b2.y;
                vx = vx >= 0.f ? vx : SLOPE * vx;
                vy = vy >= 0.f ? vy : SLOPE * vy;
                const size_t off = (size_t)row * Nout + col;
                if (res) {
                    const float2 r2 = *(const float2*)(res + off);
                    vx += r2.x; vy += r2.y;
                }
                *(float2*)(C + off) = make_float2(vx, vy);
            }
        }
    }
}

// ---------------------------------------------------------------------------
// LFA (f32 out): out[n] = [mean_k leaky(geom@wg+bg), mean_k feat[idx]]
// One warp per point, weights in registers, batched gather for MLP.
// ---------------------------------------------------------------------------
template <int D>
__global__ __launch_bounds__(256) void lfa_kernel(
    const float* __restrict__ geom, const int* __restrict__ idx,
    const float* __restrict__ feat, float* __restrict__ out,
    const float* __restrict__ wg, const float* __restrict__ bg, int N)
{
    __shared__ float sw[4][D];
    __shared__ float sb[D];
    for (int i = threadIdx.x; i < 4 * D; i += blockDim.x) sw[i / D][i % D] = wg[i];
    for (int i = threadIdx.x; i < D; i += blockDim.x) sb[i] = bg[i];
    __syncthreads();

    constexpr int DPL = D / 32;
    constexpr int KB  = (DPL == 2) ? 8 : 4;
    const int warp = threadIdx.x >> 5;
    const int lane = threadIdx.x & 31;
    const int wpb  = blockDim.x >> 5;

    float w0[DPL], w1[DPL], w2[DPL], w3[DPL], bb[DPL];
#pragma unroll
    for (int q = 0; q < DPL; q++) {
        const int d = lane + 32 * q;
        w0[q] = sw[0][d]; w1[q] = sw[1][d];
        w2[q] = sw[2][d]; w3[q] = sw[3][d];
        bb[q] = sb[d];
    }
    const float inv = 1.0f / (float)PK;

    for (int n = blockIdx.x * wpb + warp; n < N; n += gridDim.x * wpb) {
        float accG[DPL], accF[DPL];
#pragma unroll
        for (int q = 0; q < DPL; q++) { accG[q] = 0.f; accF[q] = 0.f; }

        int rows[PK];
        const int4* ip = (const int4*)(idx + (size_t)n * PK);
#pragma unroll
        for (int k4 = 0; k4 < PK / 4; k4++) {
            int4 r = ip[k4];
            rows[4 * k4 + 0] = r.x; rows[4 * k4 + 1] = r.y;
            rows[4 * k4 + 2] = r.z; rows[4 * k4 + 3] = r.w;
        }

        const float4* gp = (const float4*)(geom + (size_t)n * (PK * 4));
#pragma unroll
        for (int k = 0; k < PK; k++) {
            const float4 g = gp[k];
#pragma unroll
            for (int q = 0; q < DPL; q++) {
                float v = bb[q];
                v = fmaf(g.x, w0[q], v);
                v = fmaf(g.y, w1[q], v);
                v = fmaf(g.z, w2[q], v);
                v = fmaf(g.w, w3[q], v);
                v = v >= 0.f ? v : SLOPE * v;
                accG[q] += v;
            }
        }

#pragma unroll
        for (int kb = 0; kb < PK; kb += KB) {
            float t[KB][DPL];
#pragma unroll
            for (int j = 0; j < KB; j++) {
                const float* fr = feat + (size_t)rows[kb + j] * D;
#pragma unroll
                for (int q = 0; q < DPL; q++) t[j][q] = fr[lane + 32 * q];
            }
#pragma unroll
            for (int j = 0; j < KB; j++)
#pragma unroll
                for (int q = 0; q < DPL; q++) accF[q] += t[j][q];
        }

        float* o = out + (size_t)n * (2 * D);
#pragma unroll
        for (int q = 0; q < DPL; q++) {
            o[lane + 32 * q]     = accG[q] * inv;
            o[D + lane + 32 * q] = accF[q] * inv;
        }
    }
}

// LFA2 variant: writes split-bf16 a2 directly (feeds the final MMA GEMM)
__global__ __launch_bounds__(256) void lfa2_split_kernel(
    const float* __restrict__ geom, const int* __restrict__ idx,
    const float* __restrict__ feat, bf16* __restrict__ ohi,
    bf16* __restrict__ olo,
    const float* __restrict__ wg, const float* __restrict__ bg, int N)
{
    constexpr int D = 128;
    __shared__ float sw[4][D];
    __shared__ float sb[D];
    for (int i = threadIdx.x; i < 4 * D; i += blockDim.x) sw[i / D][i % D] = wg[i];
    for (int i = threadIdx.x; i < D; i += blockDim.x) sb[i] = bg[i];
    __syncthreads();

    constexpr int DPL = D / 32;   // 4
    constexpr int KB  = 4;
    const int warp = threadIdx.x >> 5;
    const int lane = threadIdx.x & 31;
    const int wpb  = blockDim.x >> 5;

    float w0[DPL], w1[DPL], w2[DPL], w3[DPL], bb[DPL];
#pragma unroll
    for (int q = 0; q < DPL; q++) {
        const int d = lane + 32 * q;
        w0[q] = sw[0][d]; w1[q] = sw[1][d];
        w2[q] = sw[2][d]; w3[q] = sw[3][d];
        bb[q] = sb[d];
    }
    const float inv = 1.0f / (float)PK;

    for (int n = blockIdx.x * wpb + warp; n < N; n += gridDim.x * wpb) {
        float accG[DPL], accF[DPL];
#pragma unroll
        for (int q = 0; q < DPL; q++) { accG[q] = 0.f; accF[q] = 0.f; }

        int rows[PK];
        const int4* ip = (const int4*)(idx + (size_t)n * PK);
#pragma unroll
        for (int k4 = 0; k4 < PK / 4; k4++) {
            int4 r = ip[k4];
            rows[4 * k4 + 0] = r.x; rows[4 * k4 + 1] = r.y;
            rows[4 * k4 + 2] = r.z; rows[4 * k4 + 3] = r.w;
        }

        const float4* gp = (const float4*)(geom + (size_t)n * (PK * 4));
#pragma unroll
        for (int k = 0; k < PK; k++) {
            const float4 g = gp[k];
#pragma unroll
            for (int q = 0; q < DPL; q++) {
                float v = bb[q];
                v = fmaf(g.x, w0[q], v);
                v = fmaf(g.y, w1[q], v);
                v = fmaf(g.z, w2[q], v);
                v = fmaf(g.w, w3[q], v);
                v = v >= 0.f ? v : SLOPE * v;
                accG[q] += v;
            }
        }

#pragma unroll
        for (int kb = 0; kb < PK; kb += KB) {
            float t[KB][DPL];
#pragma unroll
            for (int j = 0; j < KB; j++) {
                const float* fr = feat + (size_t)rows[kb + j] * D;
#pragma unroll
                for (int q = 0; q < DPL; q++) t[j][q] = fr[lane + 32 * q];
            }
#pragma unroll
            for (int j = 0; j < KB; j++)
#pragma unroll
                for (int q = 0; q < DPL; q++) accF[q] += t[j][q];
        }

        const size_t base = (size_t)n * (2 * D);
#pragma unroll
        for (int q = 0; q < DPL; q++) {
            bf16 h, l;
            bf16_split(accG[q] * inv, h, l);
            ohi[base + lane + 32 * q] = h;
            olo[base + lane + 32 * q] = l;
            bf16_split(accF[q] * inv, h, l);
            ohi[base + D + lane + 32 * q] = h;
            olo[base + D + lane + 32 * q] = l;
        }
    }
}

// ---------------------------------------------------------------------------
// Launch
// ---------------------------------------------------------------------------
extern "C" void kernel_launch(void* const* d_in, const int* in_sizes, int n_in,
                              void* d_out, int out_size)
{
    const float* x      = (const float*)d_in[0];
    const float* geom   = (const float*)d_in[1];
    const int*   idx    = (const int*)  d_in[2];
    const float* w_res  = (const float*)d_in[3];
    const float* b_res  = (const float*)d_in[4];
    const float* w_init = (const float*)d_in[5];
    const float* b_init = (const float*)d_in[6];
    const float* w_g1   = (const float*)d_in[7];
    const float* b_g1   = (const float*)d_in[8];
    const float* w_g2   = (const float*)d_in[9];
    const float* b_g2   = (const float*)d_in[10];
    const float* w_fin  = (const float*)d_in[11];
    const float* b_fin  = (const float*)d_in[12];
    float* out = (float*)d_out;

    float *a0, *a1;
    bf16 *xhi, *xlo, *a2hi, *a2lo;
    bf16 *wres_hi, *wres_lo, *winit_hi, *winit_lo, *wfin_hi, *wfin_lo;
    cudaGetSymbolAddress((void**)&a0, g_a0);
    cudaGetSymbolAddress((void**)&a1, g_a1);
    cudaGetSymbolAddress((void**)&xhi, g_xhi);
    cudaGetSymbolAddress((void**)&xlo, g_xlo);
    cudaGetSymbolAddress((void**)&a2hi, g_a2hi);
    cudaGetSymbolAddress((void**)&a2lo, g_a2lo);
    cudaGetSymbolAddress((void**)&wres_hi, g_wres_hi);
    cudaGetSymbolAddress((void**)&wres_lo, g_wres_lo);
    cudaGetSymbolAddress((void**)&winit_hi, g_winit_hi);
    cudaGetSymbolAddress((void**)&winit_lo, g_winit_lo);
    cudaGetSymbolAddress((void**)&wfin_hi, g_wfin_hi);
    cudaGetSymbolAddress((void**)&wfin_lo, g_wfin_lo);

    // dynamic smem: BN=128 -> 73728 B; BN=64 -> 55296 B
    constexpr int SMEM128 = 2 * (128 * 72 * 2) + 2 * (128 * 72 * 2);
    constexpr int SMEM64  = 2 * (128 * 72 * 2) + 2 * (64 * 72 * 2);
    cudaFuncSetAttribute(gemm_mma<128>, cudaFuncAttributeMaxDynamicSharedMemorySize, SMEM128);
    cudaFuncSetAttribute(gemm_mma<64>,  cudaFuncAttributeMaxDynamicSharedMemorySize, SMEM64);

    const int M = PN;
    const int mTiles = (M + 127) / 128;             // 391
    const int lfaBlocks = (M + 7) / 8;              // 6250

    // prep: split inputs / weights into bf16 hi+lo
    const int n4 = M * PDIM / 4;
    split_x_kernel<<<(n4 + 255) / 256, 256>>>(x, xhi, xlo, n4);
    transpose_split_kernel<<<(256 * 256 + 255) / 256, 256>>>(w_res, wres_hi, wres_lo, 256);
    transpose_split_kernel<<<(64 * 256 + 255) / 256, 256>>>(w_init, winit_hi, winit_lo, 64);
    transpose_split_kernel<<<(256 * 256 + 255) / 256, 256>>>(w_fin, wfin_hi, wfin_lo, 256);

    // 1) residual -> d_out (covers all outputs: un-poisons d_out)
    gemm_mma<128><<<dim3(mTiles, 2), 256, SMEM128>>>(
        xhi, xlo, wres_hi, wres_lo, b_res, nullptr, out, M, 256);
    // 2) a0 = leaky(x @ w_init + b)
    gemm_mma<64><<<dim3(mTiles, 1), 256, SMEM64>>>(
        xhi, xlo, winit_hi, winit_lo, b_init, nullptr, a0, M, 64);
    // 3) LFA1 -> a1 [N,128]
    lfa_kernel<64><<<lfaBlocks, 256>>>(geom, idx, a0, a1, w_g1, b_g1, M);
    // 4) LFA2 -> a2 split bf16 [N,256]
    lfa2_split_kernel<<<lfaBlocks, 256>>>(geom, idx, a1, a2hi, a2lo, w_g2, b_g2, M);
    // 5) out = leaky(a2 @ w_fin + b) + residual(d_out)
    gemm_mma<128><<<dim3(mTiles, 2), 256, SMEM128>>>(
        a2hi, a2lo, wfin_hi, wfin_lo, b_fin, out, out, M, 256);
}

// round 7
// speedup vs baseline: 2.0029x; 1.0735x over previous
#include <cuda_runtime.h>
#include <cuda_bf16.h>
#include <cstdint>
#include <cstddef>

// Problem constants (ResidualBlock: N=50000, K=16, DIM=256, LeakyReLU slope 0.2)
#define PN    50000
#define PK    16
#define PDIM  256
#define SLOPE 0.2f

typedef __nv_bfloat16 bf16;

// ---------------------------------------------------------------------------
// Scratch (__device__ globals; no allocations allowed)
// ---------------------------------------------------------------------------
__device__ __align__(16) float g_a0[(size_t)PN * 64];     // init MLP out [N,64]
__device__ __align__(16) float g_a1[(size_t)PN * 128];    // LFA1 out     [N,128]
__device__ __align__(16) bf16 g_xhi[(size_t)PN * 256];
__device__ __align__(16) bf16 g_xlo[(size_t)PN * 256];
__device__ __align__(16) bf16 g_a2hi[(size_t)PN * 256];
__device__ __align__(16) bf16 g_a2lo[(size_t)PN * 256];
__device__ __align__(16) bf16 g_wres_hi[256 * 256];   // transposed: [n][k]
__device__ __align__(16) bf16 g_wres_lo[256 * 256];
__device__ __align__(16) bf16 g_winit_hi[64 * 256];
__device__ __align__(16) bf16 g_winit_lo[64 * 256];
__device__ __align__(16) bf16 g_wfin_hi[256 * 256];
__device__ __align__(16) bf16 g_wfin_lo[256 * 256];

// ---------------------------------------------------------------------------
// PTX helpers (all plain-sm_103-legal: cp.async, ldmatrix, mma.sync)
// ---------------------------------------------------------------------------
__device__ __forceinline__ uint32_t smem_u32(const void* p) {
    uint32_t a;
    asm("{ .reg .u64 t; cvta.to.shared.u64 t, %1; cvt.u32.u64 %0, t; }"
        : "=r"(a) : "l"(p));
    return a;
}

#define CP16(dst, src) \
    asm volatile("cp.async.cg.shared.global [%0], [%1], 16;" \
                 :: "r"(dst), "l"(src) : "memory")
#define CP_COMMIT() asm volatile("cp.async.commit_group;" ::: "memory")
#define CP_WAIT0()  asm volatile("cp.async.wait_group 0;" ::: "memory")
#define CP_WAIT1()  asm volatile("cp.async.wait_group 1;" ::: "memory")

#define LDSM_X4(r, addr) \
    asm volatile("ldmatrix.sync.aligned.m8n8.x4.shared.b16 {%0,%1,%2,%3}, [%4];" \
                 : "=r"((r)[0]), "=r"((r)[1]), "=r"((r)[2]), "=r"((r)[3]) \
                 : "r"(addr))

#define MMA16816(d, a, b) \
    asm volatile("mma.sync.aligned.m16n8k16.row.col.f32.bf16.bf16.f32 " \
                 "{%0,%1,%2,%3},{%4,%5,%6,%7},{%8,%9},{%0,%1,%2,%3};" \
                 : "+f"((d)[0]), "+f"((d)[1]), "+f"((d)[2]), "+f"((d)[3]) \
                 : "r"((a)[0]), "r"((a)[1]), "r"((a)[2]), "r"((a)[3]), \
                   "r"((b)[0]), "r"((b)[1]))

// ---------------------------------------------------------------------------
// Prep kernels (bf16 hi/lo split)
// ---------------------------------------------------------------------------
__device__ __forceinline__ void bf16_split(float v, bf16& h, bf16& l)
{
    h = __float2bfloat16(v);
    l = __float2bfloat16(v - __bfloat162float(h));
}

__device__ __forceinline__ uint2 pack4_bf16(bf16 a, bf16 b, bf16 c, bf16 d)
{
    __nv_bfloat162 p0 = {a, b}, p1 = {c, d};
    uint2 r;
    r.x = *(uint32_t*)&p0;
    r.y = *(uint32_t*)&p1;
    return r;
}

__global__ __launch_bounds__(256) void split_x_kernel(
    const float* __restrict__ x, bf16* __restrict__ hi,
    bf16* __restrict__ lo, int n4)
{
    int i = blockIdx.x * blockDim.x + threadIdx.x;
    if (i >= n4) return;
    float4 v = ((const float4*)x)[i];
    bf16 h0, h1, h2, h3, l0, l1, l2, l3;
    bf16_split(v.x, h0, l0); bf16_split(v.y, h1, l1);
    bf16_split(v.z, h2, l2); bf16_split(v.w, h3, l3);
    ((uint2*)hi)[i] = pack4_bf16(h0, h1, h2, h3);
    ((uint2*)lo)[i] = pack4_bf16(l0, l1, l2, l3);
}

// All three weights: W[K=256, Ncols] f32 -> transposed split bf16 Wt[Ncols][256]
__global__ __launch_bounds__(256) void prep_weights(
    const float* __restrict__ w_res, const float* __restrict__ w_init,
    const float* __restrict__ w_fin,
    bf16* __restrict__ rh, bf16* __restrict__ rl,
    bf16* __restrict__ ih, bf16* __restrict__ il,
    bf16* __restrict__ fh, bf16* __restrict__ fl)
{
    int i = blockIdx.x * blockDim.x + threadIdx.x;
    bf16 h, l;
    if (i < 65536) {                                  // w_res [256,256]
        int n = i >> 8, k = i & 255;
        bf16_split(w_res[(size_t)k * 256 + n], h, l);
        rh[i] = h; rl[i] = l;
    } else if (i < 81920) {                           // w_init [256,64]
        int j = i - 65536;
        int n = j >> 8, k = j & 255;
        bf16_split(w_init[(size_t)k * 64 + n], h, l);
        ih[j] = h; il[j] = l;
    } else if (i < 147456) {                          // w_fin [256,256]
        int j = i - 81920;
        int n = j >> 8, k = j & 255;
        bf16_split(w_fin[(size_t)k * 256 + n], h, l);
        fh[j] = h; fl[j] = l;
    }
}

// ---------------------------------------------------------------------------
// Tensor-core GEMM via mma.sync (HMMA):
//   C[M,Nout] = leaky(A[M,256] @ Wt^T + bias)
// 3-pass bf16 split folded into a 12-chunk virtual-K loop, fp32 accumulators.
// CTA: BM=128 x BN x BK=64, 256 threads, warp grid 2(M) x 4(N).
// ---------------------------------------------------------------------------
template <int BN>
__global__ __launch_bounds__(256) void gemm_mma(
    const bf16* __restrict__ Ahi, const bf16* __restrict__ Alo,
    const bf16* __restrict__ Bhi, const bf16* __restrict__ Blo,
    const float* __restrict__ bias, float* __restrict__ C, int M, int Nout)
{
    constexpr int BM = 128, BK = 64, SA = BK + 8;
    constexpr int ABYTES = BM * SA * 2;
    constexpr int BBYTES = BN * SA * 2;
    constexpr int NT8 = BN / 32;
    constexpr int NPAIR = NT8 / 2;
    constexpr int NIT = 12;

    extern __shared__ __align__(16) char smem[];
    const uint32_t sa_u = smem_u32(smem);
    const uint32_t sb_u = sa_u + 2 * ABYTES;

    const int tid  = threadIdx.x;
    const int lane = tid & 31;
    const int wid  = tid >> 5;
    const int warpM0 = (wid >> 2) * 64;
    const int warpN0 = (wid & 3) * (BN / 4);
    const int row0 = blockIdx.x * BM;
    const int col0 = blockIdx.y * BN;

    const int lr = tid >> 3;
    const int lc = (tid & 7) * 8;

    float acc[4][NT8][4];
#pragma unroll
    for (int mt = 0; mt < 4; mt++)
#pragma unroll
        for (int nt = 0; nt < NT8; nt++)
#pragma unroll
            for (int j = 0; j < 4; j++) acc[mt][nt][j] = 0.f;

    auto load_tile = [&](int it, int stage) {
        const int pass = it >> 2, kc = it & 3;
        const bf16* Ap = (pass == 2) ? Alo : Ahi;
        const bf16* Bp = (pass == 1) ? Blo : Bhi;
        const int kbase = kc * BK;
#pragma unroll
        for (int i = 0; i < 4; i++) {
            int r = lr + 32 * i;
            int gr = row0 + r;
            if (gr > M - 1) gr = M - 1;
            const void* src = Ap + (size_t)gr * 256 + kbase + lc;
            CP16(sa_u + stage * ABYTES + (r * SA + lc) * 2, src);
        }
#pragma unroll
        for (int i = 0; i < BN / 32; i++) {
            int r = lr + 32 * i;
            const void* src = Bp + (size_t)(col0 + r) * 256 + kbase + lc;
            CP16(sb_u + stage * BBYTES + (r * SA + lc) * 2, src);
        }
        CP_COMMIT();
    };

    load_tile(0, 0);

    for (int it = 0; it < NIT; it++) {
        const int stage = it & 1;
        if (it + 1 < NIT) {
            load_tile(it + 1, stage ^ 1);
            CP_WAIT1();
        } else {
            CP_WAIT0();
        }
        __syncthreads();

        const uint32_t aBase = sa_u + stage * ABYTES
            + ((warpM0 + (lane & 15)) * SA + (lane >> 4) * 8) * 2;
        const uint32_t bBase = sb_u + stage * BBYTES
            + ((warpN0 + ((lane >> 4) * 8) + (lane & 7)) * SA
               + ((lane >> 3) & 1) * 8) * 2;

#pragma unroll
        for (int ks = 0; ks < 4; ks++) {
            uint32_t a[4][4];
#pragma unroll
            for (int mt = 0; mt < 4; mt++)
                LDSM_X4(a[mt], aBase + mt * (16 * SA * 2) + ks * 32);

            uint32_t b[NT8][2];
#pragma unroll
            for (int np = 0; np < NPAIR; np++) {
                uint32_t t[4];
                LDSM_X4(t, bBase + np * (16 * SA * 2) + ks * 32);
                b[2 * np][0] = t[0]; b[2 * np][1] = t[1];
                b[2 * np + 1][0] = t[2]; b[2 * np + 1][1] = t[3];
            }

#pragma unroll
            for (int mt = 0; mt < 4; mt++)
#pragma unroll
                for (int nt = 0; nt < NT8; nt++)
                    MMA16816(acc[mt][nt], a[mt], b[nt]);
        }
        __syncthreads();
    }

    const int erow = (lane >> 2);
    const int ecol = (lane & 3) * 2;
#pragma unroll
    for (int mt = 0; mt < 4; mt++) {
#pragma unroll
        for (int nt = 0; nt < NT8; nt++) {
            const int col = col0 + warpN0 + nt * 8 + ecol;
            const float2 b2 = *(const float2*)(bias + col);
#pragma unroll
            for (int h = 0; h < 2; h++) {
                const int row = row0 + warpM0 + mt * 16 + erow + h * 8;
                if (row >= M) continue;
                float vx = acc[mt][nt][2 * h]     + b2.x;
                float vy = acc[mt][nt][2 * h + 1] + b2.y;
                vx = vx >= 0.f ? vx : SLOPE * vx;
                vy = vy >= 0.f ? vy : SLOPE * vy;
                *(float2*)(C + (size_t)row * Nout + col) = make_float2(vx, vy);
            }
        }
    }
}

// ---------------------------------------------------------------------------
// Fused final GEMM: out = leaky(x@Wres+b_res) + leaky(a2@Wfin+b_fin)
// Two sequential accumulation phases sharing the smem pipeline; BN=128.
// ---------------------------------------------------------------------------
__global__ __launch_bounds__(256) void gemm_fused_final(
    const bf16* __restrict__ xhi, const bf16* __restrict__ xlo,
    const bf16* __restrict__ wrh, const bf16* __restrict__ wrl,
    const float* __restrict__ b_res,
    const bf16* __restrict__ a2hi, const bf16* __restrict__ a2lo,
    const bf16* __restrict__ wfh, const bf16* __restrict__ wfl,
    const float* __restrict__ b_fin,
    float* __restrict__ C, int M)
{
    constexpr int BM = 128, BN = 128, BK = 64, SA = BK + 8;
    constexpr int ABYTES = BM * SA * 2;
    constexpr int BBYTES = BN * SA * 2;
    constexpr int NT8 = 4, NPAIR = 2, NIT = 12;

    extern __shared__ __align__(16) char smem[];
    const uint32_t sa_u = smem_u32(smem);
    const uint32_t sb_u = sa_u + 2 * ABYTES;

    const int tid  = threadIdx.x;
    const int lane = tid & 31;
    const int wid  = tid >> 5;
    const int warpM0 = (wid >> 2) * 64;
    const int warpN0 = (wid & 3) * 32;
    const int row0 = blockIdx.x * BM;
    const int col0 = blockIdx.y * BN;

    const int lr = tid >> 3;
    const int lc = (tid & 7) * 8;

    float accR[4][NT8][4], accF[4][NT8][4];
#pragma unroll
    for (int mt = 0; mt < 4; mt++)
#pragma unroll
        for (int nt = 0; nt < NT8; nt++)
#pragma unroll
            for (int j = 0; j < 4; j++) { accR[mt][nt][j] = 0.f; accF[mt][nt][j] = 0.f; }

    auto run_phase = [&](float (&acc)[4][NT8][4],
                         const bf16* AH, const bf16* AL,
                         const bf16* BH, const bf16* BL) {
        auto load_tile = [&](int it, int stage) {
            const int pass = it >> 2, kc = it & 3;
            const bf16* Ap = (pass == 2) ? AL : AH;
            const bf16* Bp = (pass == 1) ? BL : BH;
            const int kbase = kc * BK;
#pragma unroll
            for (int i = 0; i < 4; i++) {
                int r = lr + 32 * i;
                int gr = row0 + r;
                if (gr > M - 1) gr = M - 1;
                const void* src = Ap + (size_t)gr * 256 + kbase + lc;
                CP16(sa_u + stage * ABYTES + (r * SA + lc) * 2, src);
            }
#pragma unroll
            for (int i = 0; i < 4; i++) {
                int r = lr + 32 * i;
                const void* src = Bp + (size_t)(col0 + r) * 256 + kbase + lc;
                CP16(sb_u + stage * BBYTES + (r * SA + lc) * 2, src);
            }
            CP_COMMIT();
        };

        load_tile(0, 0);
        for (int it = 0; it < NIT; it++) {
            const int stage = it & 1;
            if (it + 1 < NIT) {
                load_tile(it + 1, stage ^ 1);
                CP_WAIT1();
            } else {
                CP_WAIT0();
            }
            __syncthreads();

            const uint32_t aBase = sa_u + stage * ABYTES
                + ((warpM0 + (lane & 15)) * SA + (lane >> 4) * 8) * 2;
            const uint32_t bBase = sb_u + stage * BBYTES
                + ((warpN0 + ((lane >> 4) * 8) + (lane & 7)) * SA
                   + ((lane >> 3) & 1) * 8) * 2;

#pragma unroll
            for (int ks = 0; ks < 4; ks++) {
                uint32_t a[4][4];
#pragma unroll
                for (int mt = 0; mt < 4; mt++)
                    LDSM_X4(a[mt], aBase + mt * (16 * SA * 2) + ks * 32);

                uint32_t b[NT8][2];
#pragma unroll
                for (int np = 0; np < NPAIR; np++) {
                    uint32_t t[4];
                    LDSM_X4(t, bBase + np * (16 * SA * 2) + ks * 32);
                    b[2 * np][0] = t[0]; b[2 * np][1] = t[1];
                    b[2 * np + 1][0] = t[2]; b[2 * np + 1][1] = t[3];
                }

#pragma unroll
                for (int mt = 0; mt < 4; mt++)
#pragma unroll
                    for (int nt = 0; nt < NT8; nt++)
                        MMA16816(acc[mt][nt], a[mt], b[nt]);
            }
            __syncthreads();
        }
    };

    run_phase(accR, xhi, xlo, wrh, wrl);
    run_phase(accF, a2hi, a2lo, wfh, wfl);

    // epilogue: out = leaky(accR + b_res) + leaky(accF + b_fin)
    const int erow = (lane >> 2);
    const int ecol = (lane & 3) * 2;
#pragma unroll
    for (int mt = 0; mt < 4; mt++) {
#pragma unroll
        for (int nt = 0; nt < NT8; nt++) {
            const int col = col0 + warpN0 + nt * 8 + ecol;
            const float2 br = *(const float2*)(b_res + col);
            const float2 bfi = *(const float2*)(b_fin + col);
#pragma unroll
            for (int h = 0; h < 2; h++) {
                const int row = row0 + warpM0 + mt * 16 + erow + h * 8;
                if (row >= M) continue;
                float rx = accR[mt][nt][2 * h]     + br.x;
                float ry = accR[mt][nt][2 * h + 1] + br.y;
                rx = rx >= 0.f ? rx : SLOPE * rx;
                ry = ry >= 0.f ? ry : SLOPE * ry;
                float fx = accF[mt][nt][2 * h]     + bfi.x;
                float fy = accF[mt][nt][2 * h + 1] + bfi.y;
                fx = fx >= 0.f ? fx : SLOPE * fx;
                fy = fy >= 0.f ? fy : SLOPE * fy;
                *(float2*)(C + (size_t)row * 256 + col) =
                    make_float2(rx + fx, ry + fy);
            }
        }
    }
}

// ---------------------------------------------------------------------------
// LFA1 (D=64, f32 out [N,128]): lane owns 2 cols; one LDG.64 per gathered row.
// ---------------------------------------------------------------------------
__global__ __launch_bounds__(256) void lfa1_kernel(
    const float* __restrict__ geom, const int* __restrict__ idx,
    const float* __restrict__ feat, float* __restrict__ out,
    const float* __restrict__ wg, const float* __restrict__ bg, int N)
{
    __shared__ float sw[4][64];
    __shared__ float sb[64];
    for (int i = threadIdx.x; i < 4 * 64; i += blockDim.x) sw[i >> 6][i & 63] = wg[i];
    for (int i = threadIdx.x; i < 64; i += blockDim.x) sb[i] = bg[i];
    __syncthreads();

    const int warp = threadIdx.x >> 5;
    const int lane = threadIdx.x & 31;
    const int wpb  = blockDim.x >> 5;
    const int d0   = lane * 2;

    const float2 w0 = *(const float2*)&sw[0][d0];
    const float2 w1 = *(const float2*)&sw[1][d0];
    const float2 w2 = *(const float2*)&sw[2][d0];
    const float2 w3 = *(const float2*)&sw[3][d0];
    const float2 bb = *(const float2*)&sb[d0];
    const float inv = 1.0f / (float)PK;

    for (int n = blockIdx.x * wpb + warp; n < N; n += gridDim.x * wpb) {
        int rows[PK];
        const int4* ip = (const int4*)(idx + (size_t)n * PK);
#pragma unroll
        for (int k4 = 0; k4 < PK / 4; k4++) {
            int4 r = ip[k4];
            rows[4 * k4 + 0] = r.x; rows[4 * k4 + 1] = r.y;
            rows[4 * k4 + 2] = r.z; rows[4 * k4 + 3] = r.w;
        }

        // gather: 16 independent LDG.64 in flight
        float2 t[PK];
#pragma unroll
        for (int k = 0; k < PK; k++)
            t[k] = *(const float2*)(feat + (size_t)rows[k] * 64 + d0);

        float2 accG = {0.f, 0.f};
        const float4* gp = (const float4*)(geom + (size_t)n * (PK * 4));
#pragma unroll
        for (int k = 0; k < PK; k++) {
            const float4 g = gp[k];
            float vx = bb.x, vy = bb.y;
            vx = fmaf(g.x, w0.x, vx); vy = fmaf(g.x, w0.y, vy);
            vx = fmaf(g.y, w1.x, vx); vy = fmaf(g.y, w1.y, vy);
            vx = fmaf(g.z, w2.x, vx); vy = fmaf(g.z, w2.y, vy);
            vx = fmaf(g.w, w3.x, vx); vy = fmaf(g.w, w3.y, vy);
            vx = vx >= 0.f ? vx : SLOPE * vx;
            vy = vy >= 0.f ? vy : SLOPE * vy;
            accG.x += vx; accG.y += vy;
        }

        float2 accF = {0.f, 0.f};
#pragma unroll
        for (int k = 0; k < PK; k++) { accF.x += t[k].x; accF.y += t[k].y; }

        float* o = out + (size_t)n * 128;
        *(float2*)(o + d0)      = make_float2(accG.x * inv, accG.y * inv);
        *(float2*)(o + 64 + d0) = make_float2(accF.x * inv, accF.y * inv);
    }
}

// ---------------------------------------------------------------------------
// LFA2 (D=128): lane owns 4 cols (LDG.128 per gathered row); writes split bf16.
// ---------------------------------------------------------------------------
__global__ __launch_bounds__(256) void lfa2_split_kernel(
    const float* __restrict__ geom, const int* __restrict__ idx,
    const float* __restrict__ feat, bf16* __restrict__ ohi,
    bf16* __restrict__ olo,
    const float* __restrict__ wg, const float* __restrict__ bg, int N)
{
    __shared__ float sw[4][128];
    __shared__ float sb[128];
    for (int i = threadIdx.x; i < 4 * 128; i += blockDim.x) sw[i >> 7][i & 127] = wg[i];
    for (int i = threadIdx.x; i < 128; i += blockDim.x) sb[i] = bg[i];
    __syncthreads();

    const int warp = threadIdx.x >> 5;
    const int lane = threadIdx.x & 31;
    const int wpb  = blockDim.x >> 5;
    const int d0   = lane * 4;

    const float4 w0 = *(const float4*)&sw[0][d0];
    const float4 w1 = *(const float4*)&sw[1][d0];
    const float4 w2 = *(const float4*)&sw[2][d0];
    const float4 w3 = *(const float4*)&sw[3][d0];
    const float4 bb = *(const float4*)&sb[d0];
    const float inv = 1.0f / (float)PK;

    for (int n = blockIdx.x * wpb + warp; n < N; n += gridDim.x * wpb) {
        int rows[PK];
        const int4* ip = (const int4*)(idx + (size_t)n * PK);
#pragma unroll
        for (int k4 = 0; k4 < PK / 4; k4++) {
            int4 r = ip[k4];
            rows[4 * k4 + 0] = r.x; rows[4 * k4 + 1] = r.y;
            rows[4 * k4 + 2] = r.z; rows[4 * k4 + 3] = r.w;
        }

        float4 accF = {0.f, 0.f, 0.f, 0.f};
#pragma unroll
        for (int kb = 0; kb < PK; kb += 8) {
            float4 t[8];
#pragma unroll
            for (int j = 0; j < 8; j++)
                t[j] = *(const float4*)(feat + (size_t)rows[kb + j] * 128 + d0);
#pragma unroll
            for (int j = 0; j < 8; j++) {
                accF.x += t[j].x; accF.y += t[j].y;
                accF.z += t[j].z; accF.w += t[j].w;
            }
        }

        float4 accG = {0.f, 0.f, 0.f, 0.f};
        const float4* gp = (const float4*)(geom + (size_t)n * (PK * 4));
#pragma unroll
        for (int k = 0; k < PK; k++) {
            const float4 g = gp[k];
            float vx = bb.x, vy = bb.y, vz = bb.z, vw = bb.w;
            vx = fmaf(g.x, w0.x, vx); vy = fmaf(g.x, w0.y, vy);
            vz = fmaf(g.x, w0.z, vz); vw = fmaf(g.x, w0.w, vw);
            vx = fmaf(g.y, w1.x, vx); vy = fmaf(g.y, w1.y, vy);
            vz = fmaf(g.y, w1.z, vz); vw = fmaf(g.y, w1.w, vw);
            vx = fmaf(g.z, w2.x, vx); vy = fmaf(g.z, w2.y, vy);
            vz = fmaf(g.z, w2.z, vz); vw = fmaf(g.z, w2.w, vw);
            vx = fmaf(g.w, w3.x, vx); vy = fmaf(g.w, w3.y, vy);
            vz = fmaf(g.w, w3.z, vz); vw = fmaf(g.w, w3.w, vw);
            vx = vx >= 0.f ? vx : SLOPE * vx;
            vy = vy >= 0.f ? vy : SLOPE * vy;
            vz = vz >= 0.f ? vz : SLOPE * vz;
            vw = vw >= 0.f ? vw : SLOPE * vw;
            accG.x += vx; accG.y += vy; accG.z += vz; accG.w += vw;
        }

        const size_t base = (size_t)n * 256;
        bf16 h0, h1, h2, h3, l0, l1, l2, l3;
        bf16_split(accG.x * inv, h0, l0); bf16_split(accG.y * inv, h1, l1);
        bf16_split(accG.z * inv, h2, l2); bf16_split(accG.w * inv, h3, l3);
        *(uint2*)(ohi + base + d0) = pack4_bf16(h0, h1, h2, h3);
        *(uint2*)(olo + base + d0) = pack4_bf16(l0, l1, l2, l3);
        bf16_split(accF.x * inv, h0, l0); bf16_split(accF.y * inv, h1, l1);
        bf16_split(accF.z * inv, h2, l2); bf16_split(accF.w * inv, h3, l3);
        *(uint2*)(ohi + base + 128 + d0) = pack4_bf16(h0, h1, h2, h3);
        *(uint2*)(olo + base + 128 + d0) = pack4_bf16(l0, l1, l2, l3);
    }
}

// ---------------------------------------------------------------------------
// Launch
// ---------------------------------------------------------------------------
extern "C" void kernel_launch(void* const* d_in, const int* in_sizes, int n_in,
                              void* d_out, int out_size)
{
    const float* x      = (const float*)d_in[0];
    const float* geom   = (const float*)d_in[1];
    const int*   idx    = (const int*)  d_in[2];
    const float* w_res  = (const float*)d_in[3];
    const float* b_res  = (const float*)d_in[4];
    const float* w_init = (const float*)d_in[5];
    const float* b_init = (const float*)d_in[6];
    const float* w_g1   = (const float*)d_in[7];
    const float* b_g1   = (const float*)d_in[8];
    const float* w_g2   = (const float*)d_in[9];
    const float* b_g2   = (const float*)d_in[10];
    const float* w_fin  = (const float*)d_in[11];
    const float* b_fin  = (const float*)d_in[12];
    float* out = (float*)d_out;

    float *a0, *a1;
    bf16 *xhi, *xlo, *a2hi, *a2lo;
    bf16 *wres_hi, *wres_lo, *winit_hi, *winit_lo, *wfin_hi, *wfin_lo;
    cudaGetSymbolAddress((void**)&a0, g_a0);
    cudaGetSymbolAddress((void**)&a1, g_a1);
    cudaGetSymbolAddress((void**)&xhi, g_xhi);
    cudaGetSymbolAddress((void**)&xlo, g_xlo);
    cudaGetSymbolAddress((void**)&a2hi, g_a2hi);
    cudaGetSymbolAddress((void**)&a2lo, g_a2lo);
    cudaGetSymbolAddress((void**)&wres_hi, g_wres_hi);
    cudaGetSymbolAddress((void**)&wres_lo, g_wres_lo);
    cudaGetSymbolAddress((void**)&winit_hi, g_winit_hi);
    cudaGetSymbolAddress((void**)&winit_lo, g_winit_lo);
    cudaGetSymbolAddress((void**)&wfin_hi, g_wfin_hi);
    cudaGetSymbolAddress((void**)&wfin_lo, g_wfin_lo);

    constexpr int SMEM128 = 2 * (128 * 72 * 2) + 2 * (128 * 72 * 2);  // 73728
    constexpr int SMEM64  = 2 * (128 * 72 * 2) + 2 * (64 * 72 * 2);   // 55296
    cudaFuncSetAttribute(gemm_fused_final, cudaFuncAttributeMaxDynamicSharedMemorySize, SMEM128);
    cudaFuncSetAttribute(gemm_mma<64>, cudaFuncAttributeMaxDynamicSharedMemorySize, SMEM64);

    const int M = PN;
    const int mTiles = (M + 127) / 128;             // 391
    const int lfaBlocks = (M + 7) / 8;              // 6250

    // prep: split inputs / weights into bf16 hi+lo
    const int n4 = M * PDIM / 4;
    split_x_kernel<<<(n4 + 255) / 256, 256>>>(x, xhi, xlo, n4);
    prep_weights<<<(147456 + 255) / 256, 256>>>(w_res, w_init, w_fin,
                                                wres_hi, wres_lo,
                                                winit_hi, winit_lo,
                                                wfin_hi, wfin_lo);

    // 1) a0 = leaky(x @ w_init + b)
    gemm_mma<64><<<dim3(mTiles, 1), 256, SMEM64>>>(
        xhi, xlo, winit_hi, winit_lo, b_init, a0, M, 64);
    // 2) LFA1 -> a1 [N,128]
    lfa1_kernel<<<lfaBlocks, 256>>>(geom, idx, a0, a1, w_g1, b_g1, M);
    // 3) LFA2 -> a2 split bf16 [N,256]
    lfa2_split_kernel<<<lfaBlocks, 256>>>(geom, idx, a1, a2hi, a2lo, w_g2, b_g2, M);
    // 4) out = leaky(x@w_res+b_res) + leaky(a2@w_fin+b_fin)  (un-poisons d_out)
    gemm_fused_final<<<dim3(mTiles, 2), 256, SMEM128>>>(
        xhi, xlo, wres_hi, wres_lo, b_res,
        a2hi, a2lo, wfin_hi, wfin_lo, b_fin, out, M);
}